// round 16
// baseline (speedup 1.0000x reference)
#include <cuda_runtime.h>
#include <cuda_fp16.h>
#include <cstdint>
#include <climits>

// ---------------- problem constants ----------------
#define NVEC   65536
#define DIM    256
#define NCODE  2048
#define HW     4096
#define TOTAL_ELEMS 16777216

// rescue margin: keys are 256*dist quantized; 40/256 = 0.156 distance units (~12 sigma)
#define KMARGIN (40 * 2048)

// ---------------- GEMM config ----------------
#define MT 64           // M rows per CTA
#define NTILE 128       // N per tile
#define NSPLIT 4        // N-split factor
#define NQ 512          // N range per CTA (2048 / 4)
#define NTILES 4        // 512 / 128 per CTA
#define KCHUNKS 4       // B loaded in four 64-element K quarters per tile
#define NCHUNKS (NTILES * KCHUNKS)   // 16 chunks per CTA
#define NTHR 128        // 4 warps: warp grid 2m x 2n, warp tile 32x64

// smem layout (bytes, dynamic): A 32KB | B 16KB (single K-quarter) | wnorm 2KB
#define SM_A   0
#define SM_B   32768
#define SM_WN  49152
#define SM_TOT 51200

// ---------------- device globals ----------------
__device__ int    g_argmin[NVEC];
__device__ float  g_dist[NVEC];        // best distance (wnorm - 2*dot), approx or exact
__device__ float  g_wnorm256[NCODE];   // 256 * ||w_j||^2
__device__ float  g_xnp[8][NVEC];      // xnorm partials (8 c-blocks of 32)
__device__ float  g_part[64];
__device__ __half g_xh[(size_t)NVEC * DIM];
__device__ __half g_wh[(size_t)NCODE * DIM];
__device__ int4   g_k3[NSPLIT][NVEC];  // per-N-quarter top-3 keys per row
__device__ int    g_qcount;
__device__ int    g_qm[NVEC], g_qa[NVEC], g_qb[NVEC], g_qc[NVEC];

// ---------------- PTX helpers ----------------
static __device__ __forceinline__ uint32_t smem_u32(const void* p) {
    uint32_t a;
    asm("{ .reg .u64 t; cvta.to.shared.u64 t, %1; cvt.u32.u64 %0, t; }" : "=r"(a) : "l"(p));
    return a;
}
#define CP_ASYNC16(dst, src) \
    asm volatile("cp.async.cg.shared.global [%0], [%1], 16;" :: "r"(dst), "l"(src))
#define CP_COMMIT() asm volatile("cp.async.commit_group;" ::: "memory")
#define CP_WAIT(n)  asm volatile("cp.async.wait_group %0;" :: "n"(n) : "memory")

static __device__ __forceinline__ void ldsm4(uint32_t* r, uint32_t addr) {
    asm volatile("ldmatrix.sync.aligned.m8n8.x4.shared.b16 {%0,%1,%2,%3}, [%4];"
        : "=r"(r[0]), "=r"(r[1]), "=r"(r[2]), "=r"(r[3]) : "r"(addr));
}
static __device__ __forceinline__ void mma16816(float* c, const uint32_t* a,
                                                uint32_t b0, uint32_t b1) {
    asm volatile("mma.sync.aligned.m16n8k16.row.col.f32.f16.f16.f32 "
        "{%0,%1,%2,%3}, {%4,%5,%6,%7}, {%8,%9}, {%0,%1,%2,%3};"
        : "+f"(c[0]), "+f"(c[1]), "+f"(c[2]), "+f"(c[3])
        : "r"(a[0]), "r"(a[1]), "r"(a[2]), "r"(a[3]), "r"(b0), "r"(b1));
}

// swizzled byte offset for (row, 16B-chunk) in a 512B-per-row tile (A)
static __device__ __forceinline__ uint32_t sw_off(int row, int c16) {
    return (uint32_t)row * 512u + ((uint32_t)(c16 ^ (row & 7)) << 4);
}
// swizzled byte offset for (row, 16B-chunk) in a 128B-per-row tile (B K-quarter)
static __device__ __forceinline__ uint32_t sw_off128(int row, int c16) {
    return (uint32_t)row * 128u + ((uint32_t)(c16 ^ (row & 7)) << 4);
}

// branchless int top-2 (key encodes dist*256 in high bits, code index in low 11)
static __device__ __forceinline__ void ktop2(int k, int* b) {
    int lo = min(b[0], k), hi = max(b[0], k);
    b[0] = lo;
    b[1] = min(b[1], hi);
}
static __device__ __forceinline__ void kins3(int k, int* b) {
    if (k < b[0])      { b[2] = b[1]; b[1] = b[0]; b[0] = k; }
    else if (k < b[1]) { b[2] = b[1]; b[1] = k; }
    else if (k < b[2]) { b[2] = k; }
}
static __device__ __forceinline__ bool better(float a, int ia, float b, int ib) {
    return (a < b) || (a == b && ia < ib);
}

// ============================================================================
// Kernel 0: codebook prep — fp16 convert + 256*||w||^2 + queue reset.
// ============================================================================
__global__ void __launch_bounds__(256) wprep_kernel(const float* __restrict__ w) {
    if (blockIdx.x == 0 && threadIdx.x == 0) g_qcount = 0;
    int gwarp = (blockIdx.x * blockDim.x + threadIdx.x) >> 5;
    int lane  = threadIdx.x & 31;
    if (gwarp >= NCODE) return;
    const float4* row = reinterpret_cast<const float4*>(w + (size_t)gwarp * DIM);
    float4 v0 = row[lane];
    float4 v1 = row[lane + 32];
    __half2* dst = reinterpret_cast<__half2*>(g_wh + (size_t)gwarp * DIM);
    dst[lane * 2]      = __floats2half2_rn(v0.x, v0.y);
    dst[lane * 2 + 1]  = __floats2half2_rn(v0.z, v0.w);
    dst[64 + lane * 2]     = __floats2half2_rn(v1.x, v1.y);
    dst[64 + lane * 2 + 1] = __floats2half2_rn(v1.z, v1.w);
    float s = v0.x*v0.x + v0.y*v0.y + v0.z*v0.z + v0.w*v0.w
            + v1.x*v1.x + v1.y*v1.y + v1.z*v1.z + v1.w*v1.w;
    #pragma unroll
    for (int o = 16; o > 0; o >>= 1)
        s += __shfl_xor_sync(0xFFFFFFFF, s, o);
    if (lane == 0) g_wnorm256[gwarp] = s * 256.0f;
}

// ============================================================================
// Kernel 1: x transpose [b][c][hw] -> g_xh[m][c] fp16, plus xnorm partials.
// ============================================================================
__global__ void __launch_bounds__(256) xsplit_kernel(const float* __restrict__ x) {
    __shared__ float t[32][33];
    int bx = blockIdx.x, by = blockIdx.y, b = blockIdx.z;
    int tx = threadIdx.x & 31, ty = threadIdx.x >> 5;
    const float* xp = x + (size_t)b * (DIM * HW) + (size_t)(by * 32) * HW + bx * 32;
    #pragma unroll
    for (int i = 0; i < 4; ++i)
        t[ty + i * 8][tx] = xp[(size_t)(ty + i * 8) * HW + tx];
    __syncthreads();
    #pragma unroll
    for (int i = 0; i < 4; ++i) {
        int hwr = ty + i * 8;
        int m = b * HW + bx * 32 + hwr;
        float v = t[tx][hwr];
        g_xh[(size_t)m * DIM + by * 32 + tx] = __float2half_rn(v);
        float q = v * v;
        #pragma unroll
        for (int o = 16; o > 0; o >>= 1)
            q += __shfl_xor_sync(0xFFFFFFFF, q, o);
        if (tx == 0) g_xnp[by][m] = q;
    }
}

// ============================================================================
// Kernel 2: fp16 HMMA distance GEMM + fused per-quarter top-3 argmin.
// Grid 4096: blockIdx.x = (m_tile << 2) | n_quarter. CTA: 64 rows x 512 codes.
// 128 threads / 4 warps (2m x 2n, warp tile 32x64); 4 CTAs/SM via 16KB
// single-buffer K-quarter B chunks — 3 peer CTAs hide load + epilogue phases.
// key = rint(256*dist)*2048 + n ; dist = ||w||^2 - 2*(x.w)
// ============================================================================
static __device__ __forceinline__ void load_b_chunk(uint32_t dstbase, int n0, int kq, int tid) {
    const __half* bsrc = g_wh + (size_t)n0 * DIM + kq * 64;
    #pragma unroll
    for (int it = 0; it < 8; ++it) {
        int id = tid + it * NTHR;
        int row = id >> 3, c16 = id & 7;
        CP_ASYNC16(dstbase + sw_off128(row, c16), bsrc + (size_t)row * DIM + c16 * 8);
    }
    CP_COMMIT();
}

__global__ void __launch_bounds__(NTHR, 4) mma_argmin_kernel() {
    extern __shared__ char smem[];
    const uint32_t sb = smem_u32(smem);
    const uint32_t sA = sb + SM_A;
    const uint32_t sB = sb + SM_B;
    float* wns = reinterpret_cast<float*>(smem + SM_WN);   // 256*wnorm, this quarter

    const int tid = threadIdx.x;
    const int lane = tid & 31, wid = tid >> 5;
    const int warp_m = wid & 1;      // 2 m-halves of 32 rows
    const int warp_n = wid >> 1;     // 2 n-halves of 64 cols
    const int m0 = (blockIdx.x >> 2) * MT;
    const int nq = blockIdx.x & 3;
    const int nb0 = nq * NQ;         // N range base

    // pre-scaled wnorm for this quarter -> smem (indexed by local n)
    #pragma unroll
    for (int i = tid; i < NQ; i += NTHR) wns[i] = g_wnorm256[nb0 + i];

    // A tile (64 x 256 fp16 = 32KB) via cp.async
    {
        const __half* asrc = g_xh + (size_t)m0 * DIM;
        #pragma unroll
        for (int it = 0; it < 16; ++it) {
            int id = tid + it * NTHR;
            int row = id >> 5, c16 = id & 31;
            CP_ASYNC16(sA + sw_off(row, c16), asrc + (size_t)row * DIM + c16 * 8);
        }
        CP_COMMIT();
    }
    load_b_chunk(sB, nb0, 0, tid);   // chunk 0 (tile 0, kq 0)

    // per-thread fragment address components (thread-invariant parts)
    const int a_rbase = warp_m * 32 + (lane & 15);                       // + mf*16
    const int a_e     = lane >> 4;                                       // A c16 = kstep*2 + a_e
    const int b_rbase = warp_n * 64 + (lane & 7) + ((lane >> 4) << 3);   // + ng*16
    const int b_e     = (lane >> 3) & 1;                                 // B c16 = ks*2 + b_e

    // per-thread top-2 int keys for 4 row-slots (slot = mf*2 + half)
    int kk[4][2];
    #pragma unroll
    for (int s = 0; s < 4; ++s) { kk[s][0] = INT_MAX; kk[s][1] = INT_MAX; }

    #pragma unroll 1
    for (int nt = 0; nt < NTILES; ++nt) {
        float acc[2][8][4];
        #pragma unroll
        for (int mf = 0; mf < 2; ++mf)
            #pragma unroll
            for (int nf = 0; nf < 8; ++nf)
                #pragma unroll
                for (int c = 0; c < 4; ++c) acc[mf][nf][c] = 0.f;

        #pragma unroll
        for (int h = 0; h < KCHUNKS; ++h) {
            const int g = nt * KCHUNKS + h;
            CP_WAIT(0);
            __syncthreads();             // chunk g (and A, first pass) visible

            #pragma unroll
            for (int ks = 0; ks < 4; ++ks) {
                const int ac16 = h * 8 + ks * 2 + a_e;    // global K chunk in A
                uint32_t a0[4], a1[4];
                ldsm4(a0, sA + sw_off(a_rbase,      ac16));
                ldsm4(a1, sA + sw_off(a_rbase + 16, ac16));
                #pragma unroll
                for (int ng = 0; ng < 4; ++ng) {
                    uint32_t br[4];
                    ldsm4(br, sB + sw_off128(b_rbase + ng * 16, ks * 2 + b_e));
                    mma16816(acc[0][ng * 2],     a0, br[0], br[1]);
                    mma16816(acc[0][ng * 2 + 1], a0, br[2], br[3]);
                    mma16816(acc[1][ng * 2],     a1, br[0], br[1]);
                    mma16816(acc[1][ng * 2 + 1], a1, br[2], br[3]);
                }
            }

            __syncthreads();             // all warps done reading sB
            const int nxt = g + 1;
            if (nxt < NCHUNKS)           // refill buffer; load spans epilogue too
                load_b_chunk(sB, nb0 + (nxt >> 2) * NTILE, nxt & 3, tid);
        }

        // epilogue: int-key distance + branchless top-2 (keys carry GLOBAL n)
        #pragma unroll
        for (int nf = 0; nf < 8; ++nf) {
            int nl = nt * NTILE + warp_n * 64 + nf * 8 + 2 * (lane & 3);   // local n
            int n  = nb0 + nl;                                             // global n
            float wn0 = wns[nl], wn1 = wns[nl + 1];
            #pragma unroll
            for (int mf = 0; mf < 2; ++mf) {
                int k0 = __float2int_rn(fmaf(-512.f, acc[mf][nf][0], wn0)) * 2048 + n;
                int k1 = __float2int_rn(fmaf(-512.f, acc[mf][nf][1], wn1)) * 2048 + (n + 1);
                int k2 = __float2int_rn(fmaf(-512.f, acc[mf][nf][2], wn0)) * 2048 + n;
                int k3 = __float2int_rn(fmaf(-512.f, acc[mf][nf][3], wn1)) * 2048 + (n + 1);
                ktop2(k0, kk[mf * 2]);
                ktop2(k1, kk[mf * 2]);
                ktop2(k2, kk[mf * 2 + 1]);
                ktop2(k3, kk[mf * 2 + 1]);
            }
        }
    }

    // cross-thread reduction: 8 slots per row, each slot carries top-2 keys
    __syncthreads();
    int2* red = reinterpret_cast<int2*>(smem);   // reuse A region: 64*8*8B = 4KB
    #pragma unroll
    for (int s = 0; s < 4; ++s) {
        int mf = s >> 1, half = s & 1;
        int row = warp_m * 32 + mf * 16 + half * 8 + (lane >> 2);
        int slot = warp_n * 4 + (lane & 3);
        red[row * 8 + slot] = make_int2(kk[s][0], kk[s][1]);
    }
    __syncthreads();
    if (tid < MT) {
        int b[3] = { INT_MAX, INT_MAX, INT_MAX };
        #pragma unroll
        for (int s = 0; s < 8; ++s) {
            int2 e = red[tid * 8 + s];
            kins3(e.x, b);
            kins3(e.y, b);
        }
        g_k3[nq][m0 + tid] = make_int4(b[0], b[1], b[2], 0);
    }
}

// ============================================================================
// Kernel 3: merge the four N-quarter top-3 lists -> global argmin/dist/queue.
// ============================================================================
__global__ void __launch_bounds__(256)
merge_kernel() {
    const int m = blockIdx.x * 256 + threadIdx.x;   // grid 256 -> 65536
    int b[3] = { INT_MAX, INT_MAX, INT_MAX };
    #pragma unroll
    for (int q = 0; q < NSPLIT; ++q) {
        int4 a = g_k3[q][m];
        kins3(a.x, b); kins3(a.y, b); kins3(a.z, b);
    }
    g_argmin[m] = b[0] & 2047;
    g_dist[m] = (float)(b[0] >> 11) * (1.0f / 256.0f);
    if (b[1] - b[0] < KMARGIN) {
        int p = atomicAdd(&g_qcount, 1);
        g_qm[p] = m; g_qa[p] = b[0] & 2047; g_qb[p] = b[1] & 2047; g_qc[p] = b[2] & 2047;
    }
}

// ============================================================================
// Kernel 4: exact fp32 rescue among top-3 candidates (small queue).
// ============================================================================
__global__ void __launch_bounds__(256)
rescue_kernel(const float* __restrict__ x, const float* __restrict__ w) {
    const int gw = (blockIdx.x * blockDim.x + threadIdx.x) >> 5;
    const int lane = threadIdx.x & 31;
    const int nw = (gridDim.x * blockDim.x) >> 5;
    const int cnt = g_qcount;
    for (int i = gw; i < cnt; i += nw) {
        int m = g_qm[i], ja = g_qa[i], jb = g_qb[i], jc = g_qc[i];
        int b = m >> 12, hw = m & (HW - 1);
        const float* xp = x + (size_t)b * (DIM * HW) + hw;
        const float* wa = w + (size_t)ja * DIM;
        const float* wb = w + (size_t)jb * DIM;
        const float* wc = w + (size_t)jc * DIM;
        float xv[8];
        #pragma unroll
        for (int r = 0; r < 8; ++r)
            xv[r] = xp[(size_t)(lane + r * 32) * HW];
        float sa = 0.f, sb2 = 0.f, sc = 0.f;
        #pragma unroll
        for (int r = 0; r < 8; ++r) {
            int c = lane + r * 32;
            sa  = fmaf(xv[r], wa[c], sa);
            sb2 = fmaf(xv[r], wb[c], sb2);
            sc  = fmaf(xv[r], wc[c], sc);
        }
        #pragma unroll
        for (int o = 16; o > 0; o >>= 1) {
            sa  += __shfl_xor_sync(0xFFFFFFFF, sa, o);
            sb2 += __shfl_xor_sync(0xFFFFFFFF, sb2, o);
            sc  += __shfl_xor_sync(0xFFFFFFFF, sc, o);
        }
        if (lane == 0) {
            float da = fmaf(-2.0f, sa,  g_wnorm256[ja] * (1.0f / 256.0f));
            float db = fmaf(-2.0f, sb2, g_wnorm256[jb] * (1.0f / 256.0f));
            float dc = fmaf(-2.0f, sc,  g_wnorm256[jc] * (1.0f / 256.0f));
            float wv = da; int wi = ja;
            if (better(db, jb, wv, wi)) { wv = db; wi = jb; }
            if (better(dc, jc, wv, wi)) { wv = dc; wi = jc; }
            g_argmin[m] = wi;
            g_dist[m] = wv;
        }
    }
}

// ============================================================================
// Kernel 5: smem-transposed gather — coalesced codebook reads AND output writes.
// ============================================================================
__global__ void __launch_bounds__(256)
gather_kernel(const float* __restrict__ w, float* __restrict__ out) {
    __shared__ float sm[DIM][33];
    __shared__ int js[32];
    const int t = threadIdx.x;
    const int m0 = blockIdx.x * 32;            // grid 2048
    if (t < 32) js[t] = g_argmin[m0 + t];
    __syncthreads();

    #pragma unroll
    for (int p4 = 0; p4 < 32; p4 += 4) {
        float v0 = w[(size_t)js[p4 + 0] * DIM + t];
        float v1 = w[(size_t)js[p4 + 1] * DIM + t];
        float v2 = w[(size_t)js[p4 + 2] * DIM + t];
        float v3 = w[(size_t)js[p4 + 3] * DIM + t];
        sm[t][p4 + 0] = v0;
        sm[t][p4 + 1] = v1;
        sm[t][p4 + 2] = v2;
        sm[t][p4 + 3] = v3;
    }
    __syncthreads();

    const int b = m0 >> 12, hw0 = m0 & (HW - 1);
    float* op = out + (size_t)b * (DIM * HW) + hw0;
    const int lane = t & 31, wrp = t >> 5;
    #pragma unroll
    for (int i = 0; i < 32; ++i) {
        int c = wrp * 32 + i;
        op[(size_t)c * HW + lane] = sm[c][lane];
    }
}

// ============================================================================
// Kernel 6/7: loss = 0.25 * sum_m(dist[m] + xnorm[m]) / TOTAL_ELEMS
// ============================================================================
__global__ void __launch_bounds__(256)
losspart_kernel() {
    __shared__ float red[256];
    const int t = threadIdx.x;
    const int gt = blockIdx.x * 256 + t;     // 16384 threads
    float s = 0.f;
    #pragma unroll
    for (int r = 0; r < 4; ++r) {
        int m = gt + r * 16384;
        float xn = g_dist[m];
        #pragma unroll
        for (int by = 0; by < 8; ++by) xn += g_xnp[by][m];
        s += xn;
    }
    red[t] = s;
    __syncthreads();
    #pragma unroll
    for (int o = 128; o > 0; o >>= 1) {
        if (t < o) red[t] += red[t + o];
        __syncthreads();
    }
    if (t == 0) g_part[blockIdx.x] = red[0];
}

__global__ void __launch_bounds__(64)
finalize_kernel(float* __restrict__ out, int loss_idx) {
    __shared__ float red[64];
    const int t = threadIdx.x;
    red[t] = g_part[t];
    __syncthreads();
    #pragma unroll
    for (int o = 32; o > 0; o >>= 1) {
        if (t < o) red[t] += red[t + o];
        __syncthreads();
    }
    if (t == 0)
        out[loss_idx] = 0.25f * red[0] / (float)TOTAL_ELEMS;
}

// ============================================================================
extern "C" void kernel_launch(void* const* d_in, const int* in_sizes, int n_in,
                              void* d_out, int out_size) {
    const float* x = (const float*)d_in[0];   // [16,256,64,64]
    const float* w = (const float*)d_in[1];   // [2048,256]
    float* out = (float*)d_out;

    cudaFuncSetAttribute(mma_argmin_kernel,
                         cudaFuncAttributeMaxDynamicSharedMemorySize, SM_TOT);

    wprep_kernel<<<NCODE * 32 / 256, 256>>>(w);
    xsplit_kernel<<<dim3(HW / 32, DIM / 32, 16), 256>>>(x);
    mma_argmin_kernel<<<(NVEC / MT) * NSPLIT, NTHR, SM_TOT>>>();
    merge_kernel<<<NVEC / 256, 256>>>();
    rescue_kernel<<<96, 256>>>(x, w);
    gather_kernel<<<NVEC / 32, 256>>>(w, out);
    losspart_kernel<<<64, 256>>>();
    finalize_kernel<<<1, 64>>>(out, out_size - 1);
}

// round 17
// speedup vs baseline: 1.4901x; 1.4901x over previous
#include <cuda_runtime.h>
#include <cuda_fp16.h>
#include <cstdint>
#include <climits>

// ---------------- problem constants ----------------
#define NVEC   65536
#define DIM    256
#define NCODE  2048
#define HW     4096
#define TOTAL_ELEMS 16777216

// rescue margin: keys are 256*dist quantized; 40/256 = 0.156 distance units (~12 sigma)
#define KMARGIN (40 * 2048)

// ---------------- GEMM config ----------------
#define MT 64           // M rows per CTA
#define NTILE 128       // N per tile
#define NSPLIT 4        // N-split factor
#define NQ 512          // N range per CTA (2048 / 4)
#define NTILES 4        // 512 / 128 per CTA
#define KHALVES 2       // B loaded in two 128-element K halves
#define NTHR 128        // 4 warps: warp grid 2m x 2n, warp tile 32x64

// smem layout (bytes, dynamic): A 32KB | B 32KB (one K-half) | wnorm 2KB
#define SM_A   0
#define SM_B   32768
#define SM_WN  65536
#define SM_TOT 67584

// ---------------- device globals ----------------
__device__ int    g_argmin[NVEC];
__device__ float  g_dist[NVEC];        // best distance (wnorm - 2*dot), approx or exact
__device__ float  g_wnorm256[NCODE];   // 256 * ||w_j||^2
__device__ float  g_xnp[8][NVEC];      // xnorm partials (8 c-blocks of 32)
__device__ float  g_part[64];
__device__ __half g_xh[(size_t)NVEC * DIM];
__device__ __half g_wh[(size_t)NCODE * DIM];
__device__ int4   g_k3[NSPLIT][NVEC];  // per-N-quarter top-3 keys per row
__device__ int    g_qcount;
__device__ int    g_qm[NVEC], g_qa[NVEC], g_qb[NVEC], g_qc[NVEC];

// ---------------- PTX helpers ----------------
static __device__ __forceinline__ uint32_t smem_u32(const void* p) {
    uint32_t a;
    asm("{ .reg .u64 t; cvta.to.shared.u64 t, %1; cvt.u32.u64 %0, t; }" : "=r"(a) : "l"(p));
    return a;
}
#define CP_ASYNC16(dst, src) \
    asm volatile("cp.async.cg.shared.global [%0], [%1], 16;" :: "r"(dst), "l"(src))
#define CP_COMMIT() asm volatile("cp.async.commit_group;" ::: "memory")
#define CP_WAIT(n)  asm volatile("cp.async.wait_group %0;" :: "n"(n) : "memory")

static __device__ __forceinline__ void ldsm4(uint32_t* r, uint32_t addr) {
    asm volatile("ldmatrix.sync.aligned.m8n8.x4.shared.b16 {%0,%1,%2,%3}, [%4];"
        : "=r"(r[0]), "=r"(r[1]), "=r"(r[2]), "=r"(r[3]) : "r"(addr));
}
static __device__ __forceinline__ void mma16816(float* c, const uint32_t* a,
                                                uint32_t b0, uint32_t b1) {
    asm volatile("mma.sync.aligned.m16n8k16.row.col.f32.f16.f16.f32 "
        "{%0,%1,%2,%3}, {%4,%5,%6,%7}, {%8,%9}, {%0,%1,%2,%3};"
        : "+f"(c[0]), "+f"(c[1]), "+f"(c[2]), "+f"(c[3])
        : "r"(a[0]), "r"(a[1]), "r"(a[2]), "r"(a[3]), "r"(b0), "r"(b1));
}

// swizzled byte offset for (row, 16B-chunk) in a 512B-per-row tile (A)
static __device__ __forceinline__ uint32_t sw_off(int row, int c16) {
    return (uint32_t)row * 512u + ((uint32_t)(c16 ^ (row & 7)) << 4);
}
// swizzled byte offset for (row, 16B-chunk) in a 256B-per-row tile (B K-half)
static __device__ __forceinline__ uint32_t sw_off256(int row, int c16) {
    return (uint32_t)row * 256u + ((uint32_t)(c16 ^ (row & 7)) << 4);
}

// branchless int top-2 (key encodes dist*256 in high bits, code index in low 11)
static __device__ __forceinline__ void ktop2(int k, int* b) {
    int lo = min(b[0], k), hi = max(b[0], k);
    b[0] = lo;
    b[1] = min(b[1], hi);
}
static __device__ __forceinline__ void kins3(int k, int* b) {
    if (k < b[0])      { b[2] = b[1]; b[1] = b[0]; b[0] = k; }
    else if (k < b[1]) { b[2] = b[1]; b[1] = k; }
    else if (k < b[2]) { b[2] = k; }
}
static __device__ __forceinline__ bool better(float a, int ia, float b, int ib) {
    return (a < b) || (a == b && ia < ib);
}

// ============================================================================
// Kernel 0: codebook prep — fp16 convert + 256*||w||^2 + queue reset.
// ============================================================================
__global__ void __launch_bounds__(256) wprep_kernel(const float* __restrict__ w) {
    if (blockIdx.x == 0 && threadIdx.x == 0) g_qcount = 0;
    int gwarp = (blockIdx.x * blockDim.x + threadIdx.x) >> 5;
    int lane  = threadIdx.x & 31;
    if (gwarp >= NCODE) return;
    const float4* row = reinterpret_cast<const float4*>(w + (size_t)gwarp * DIM);
    float4 v0 = row[lane];
    float4 v1 = row[lane + 32];
    __half2* dst = reinterpret_cast<__half2*>(g_wh + (size_t)gwarp * DIM);
    dst[lane * 2]      = __floats2half2_rn(v0.x, v0.y);
    dst[lane * 2 + 1]  = __floats2half2_rn(v0.z, v0.w);
    dst[64 + lane * 2]     = __floats2half2_rn(v1.x, v1.y);
    dst[64 + lane * 2 + 1] = __floats2half2_rn(v1.z, v1.w);
    float s = v0.x*v0.x + v0.y*v0.y + v0.z*v0.z + v0.w*v0.w
            + v1.x*v1.x + v1.y*v1.y + v1.z*v1.z + v1.w*v1.w;
    #pragma unroll
    for (int o = 16; o > 0; o >>= 1)
        s += __shfl_xor_sync(0xFFFFFFFF, s, o);
    if (lane == 0) g_wnorm256[gwarp] = s * 256.0f;
}

// ============================================================================
// Kernel 1: x transpose [b][c][hw] -> g_xh[m][c] fp16, plus xnorm partials.
// ============================================================================
__global__ void __launch_bounds__(256) xsplit_kernel(const float* __restrict__ x) {
    __shared__ float t[32][33];
    int bx = blockIdx.x, by = blockIdx.y, b = blockIdx.z;
    int tx = threadIdx.x & 31, ty = threadIdx.x >> 5;
    const float* xp = x + (size_t)b * (DIM * HW) + (size_t)(by * 32) * HW + bx * 32;
    #pragma unroll
    for (int i = 0; i < 4; ++i)
        t[ty + i * 8][tx] = xp[(size_t)(ty + i * 8) * HW + tx];
    __syncthreads();
    #pragma unroll
    for (int i = 0; i < 4; ++i) {
        int hwr = ty + i * 8;
        int m = b * HW + bx * 32 + hwr;
        float v = t[tx][hwr];
        g_xh[(size_t)m * DIM + by * 32 + tx] = __float2half_rn(v);
        float q = v * v;
        #pragma unroll
        for (int o = 16; o > 0; o >>= 1)
            q += __shfl_xor_sync(0xFFFFFFFF, q, o);
        if (tx == 0) g_xnp[by][m] = q;
    }
}

// ============================================================================
// Kernel 2: fp16 HMMA distance GEMM + fused per-quarter top-3 argmin.
// Grid 4096: blockIdx.x = (m_tile << 2) | n_quarter. CTA: 64 rows x 512 codes.
// 128 threads / 4 warps (2m x 2n, warp tile 32x64); 3 CTAs per SM via K-split
// single-buffer B (32KB halves) — peer CTAs hide epilogue + load latency.
// key = rint(256*dist)*2048 + n ; dist = ||w||^2 - 2*(x.w)
// ============================================================================
static __device__ __forceinline__ void load_b_half(uint32_t dstbase, int n0, int kh, int tid) {
    const __half* bsrc = g_wh + (size_t)n0 * DIM + kh * 128;
    #pragma unroll
    for (int it = 0; it < 16; ++it) {
        int id = tid + it * NTHR;
        int row = id >> 4, c16 = id & 15;
        CP_ASYNC16(dstbase + sw_off256(row, c16), bsrc + (size_t)row * DIM + c16 * 8);
    }
    CP_COMMIT();
}

__global__ void __launch_bounds__(NTHR, 3) mma_argmin_kernel() {
    extern __shared__ char smem[];
    const uint32_t sb = smem_u32(smem);
    const uint32_t sA = sb + SM_A;
    const uint32_t sB = sb + SM_B;
    float* wns = reinterpret_cast<float*>(smem + SM_WN);   // 256*wnorm, this quarter

    const int tid = threadIdx.x;
    const int lane = tid & 31, wid = tid >> 5;
    const int warp_m = wid & 1;      // 2 m-halves of 32 rows
    const int warp_n = wid >> 1;     // 2 n-halves of 64 cols
    const int m0 = (blockIdx.x >> 2) * MT;
    const int nq = blockIdx.x & 3;
    const int nb0 = nq * NQ;         // N range base

    // pre-scaled wnorm for this quarter -> smem (indexed by local n)
    #pragma unroll
    for (int i = tid; i < NQ; i += NTHR) wns[i] = g_wnorm256[nb0 + i];

    // A tile (64 x 256 fp16 = 32KB) via cp.async
    {
        const __half* asrc = g_xh + (size_t)m0 * DIM;
        #pragma unroll
        for (int it = 0; it < 16; ++it) {
            int id = tid + it * NTHR;
            int row = id >> 5, c16 = id & 31;
            CP_ASYNC16(sA + sw_off(row, c16), asrc + (size_t)row * DIM + c16 * 8);
        }
        CP_COMMIT();
    }
    load_b_half(sB, nb0, 0, tid);    // tile 0, K-half 0

    // per-thread fragment address components (thread-invariant parts)
    const int a_rbase = warp_m * 32 + (lane & 15);                       // + mf*16
    const int a_e     = lane >> 4;                                       // A c16 = kstep*2 + a_e
    const int b_rbase = warp_n * 64 + (lane & 7) + ((lane >> 4) << 3);   // + ng*16
    const int b_e     = (lane >> 3) & 1;                                 // B c16 = ks*2 + b_e

    // per-thread top-2 int keys for 4 row-slots (slot = mf*2 + half)
    int kk[4][2];
    #pragma unroll
    for (int s = 0; s < 4; ++s) { kk[s][0] = INT_MAX; kk[s][1] = INT_MAX; }

    #pragma unroll 1
    for (int nt = 0; nt < NTILES; ++nt) {
        float acc[2][8][4];
        #pragma unroll
        for (int mf = 0; mf < 2; ++mf)
            #pragma unroll
            for (int nf = 0; nf < 8; ++nf)
                #pragma unroll
                for (int c = 0; c < 4; ++c) acc[mf][nf][c] = 0.f;

        #pragma unroll
        for (int h = 0; h < KHALVES; ++h) {
            CP_WAIT(0);
            __syncthreads();             // B half (and A, first pass) visible

            #pragma unroll
            for (int ks = 0; ks < 8; ++ks) {
                const int ac16 = h * 16 + ks * 2 + a_e;   // global K chunk in A
                uint32_t a0[4], a1[4];
                ldsm4(a0, sA + sw_off(a_rbase,      ac16));
                ldsm4(a1, sA + sw_off(a_rbase + 16, ac16));
                #pragma unroll
                for (int ng = 0; ng < 4; ++ng) {
                    uint32_t br[4];
                    ldsm4(br, sB + sw_off256(b_rbase + ng * 16, ks * 2 + b_e));
                    mma16816(acc[0][ng * 2],     a0, br[0], br[1]);
                    mma16816(acc[0][ng * 2 + 1], a0, br[2], br[3]);
                    mma16816(acc[1][ng * 2],     a1, br[0], br[1]);
                    mma16816(acc[1][ng * 2 + 1], a1, br[2], br[3]);
                }
            }

            __syncthreads();             // all warps done reading sB
            const int nxt = nt * 2 + h + 1;
            if (nxt < NTILES * 2)        // issue next K-half load before epilogue
                load_b_half(sB, nb0 + (nxt >> 1) * NTILE, nxt & 1, tid);
        }

        // epilogue: int-key distance + branchless top-2 (keys carry GLOBAL n)
        #pragma unroll
        for (int nf = 0; nf < 8; ++nf) {
            int nl = nt * NTILE + warp_n * 64 + nf * 8 + 2 * (lane & 3);   // local n
            int n  = nb0 + nl;                                             // global n
            float wn0 = wns[nl], wn1 = wns[nl + 1];
            #pragma unroll
            for (int mf = 0; mf < 2; ++mf) {
                int k0 = __float2int_rn(fmaf(-512.f, acc[mf][nf][0], wn0)) * 2048 + n;
                int k1 = __float2int_rn(fmaf(-512.f, acc[mf][nf][1], wn1)) * 2048 + (n + 1);
                int k2 = __float2int_rn(fmaf(-512.f, acc[mf][nf][2], wn0)) * 2048 + n;
                int k3 = __float2int_rn(fmaf(-512.f, acc[mf][nf][3], wn1)) * 2048 + (n + 1);
                ktop2(k0, kk[mf * 2]);
                ktop2(k1, kk[mf * 2]);
                ktop2(k2, kk[mf * 2 + 1]);
                ktop2(k3, kk[mf * 2 + 1]);
            }
        }
    }

    // cross-thread reduction: 8 slots per row, each slot carries top-2 keys
    __syncthreads();
    int2* red = reinterpret_cast<int2*>(smem);   // reuse A region: 64*8*8B = 4KB
    #pragma unroll
    for (int s = 0; s < 4; ++s) {
        int mf = s >> 1, half = s & 1;
        int row = warp_m * 32 + mf * 16 + half * 8 + (lane >> 2);
        int slot = warp_n * 4 + (lane & 3);
        red[row * 8 + slot] = make_int2(kk[s][0], kk[s][1]);
    }
    __syncthreads();
    if (tid < MT) {
        int b[3] = { INT_MAX, INT_MAX, INT_MAX };
        #pragma unroll
        for (int s = 0; s < 8; ++s) {
            int2 e = red[tid * 8 + s];
            kins3(e.x, b);
            kins3(e.y, b);
        }
        g_k3[nq][m0 + tid] = make_int4(b[0], b[1], b[2], 0);
    }
}

// ============================================================================
// Kernel 3: merge the four N-quarter top-3 lists -> global argmin/dist/queue.
// ============================================================================
__global__ void __launch_bounds__(256)
merge_kernel() {
    const int m = blockIdx.x * 256 + threadIdx.x;   // grid 256 -> 65536
    int b[3] = { INT_MAX, INT_MAX, INT_MAX };
    #pragma unroll
    for (int q = 0; q < NSPLIT; ++q) {
        int4 a = g_k3[q][m];
        kins3(a.x, b); kins3(a.y, b); kins3(a.z, b);
    }
    g_argmin[m] = b[0] & 2047;
    g_dist[m] = (float)(b[0] >> 11) * (1.0f / 256.0f);
    if (b[1] - b[0] < KMARGIN) {
        int p = atomicAdd(&g_qcount, 1);
        g_qm[p] = m; g_qa[p] = b[0] & 2047; g_qb[p] = b[1] & 2047; g_qc[p] = b[2] & 2047;
    }
}

// ============================================================================
// Kernel 4: exact fp32 rescue among top-3 candidates (small queue).
// ============================================================================
__global__ void __launch_bounds__(256)
rescue_kernel(const float* __restrict__ x, const float* __restrict__ w) {
    const int gw = (blockIdx.x * blockDim.x + threadIdx.x) >> 5;
    const int lane = threadIdx.x & 31;
    const int nw = (gridDim.x * blockDim.x) >> 5;
    const int cnt = g_qcount;
    for (int i = gw; i < cnt; i += nw) {
        int m = g_qm[i], ja = g_qa[i], jb = g_qb[i], jc = g_qc[i];
        int b = m >> 12, hw = m & (HW - 1);
        const float* xp = x + (size_t)b * (DIM * HW) + hw;
        const float* wa = w + (size_t)ja * DIM;
        const float* wb = w + (size_t)jb * DIM;
        const float* wc = w + (size_t)jc * DIM;
        float xv[8];
        #pragma unroll
        for (int r = 0; r < 8; ++r)
            xv[r] = xp[(size_t)(lane + r * 32) * HW];
        float sa = 0.f, sb2 = 0.f, sc = 0.f;
        #pragma unroll
        for (int r = 0; r < 8; ++r) {
            int c = lane + r * 32;
            sa  = fmaf(xv[r], wa[c], sa);
            sb2 = fmaf(xv[r], wb[c], sb2);
            sc  = fmaf(xv[r], wc[c], sc);
        }
        #pragma unroll
        for (int o = 16; o > 0; o >>= 1) {
            sa  += __shfl_xor_sync(0xFFFFFFFF, sa, o);
            sb2 += __shfl_xor_sync(0xFFFFFFFF, sb2, o);
            sc  += __shfl_xor_sync(0xFFFFFFFF, sc, o);
        }
        if (lane == 0) {
            float da = fmaf(-2.0f, sa,  g_wnorm256[ja] * (1.0f / 256.0f));
            float db = fmaf(-2.0f, sb2, g_wnorm256[jb] * (1.0f / 256.0f));
            float dc = fmaf(-2.0f, sc,  g_wnorm256[jc] * (1.0f / 256.0f));
            float wv = da; int wi = ja;
            if (better(db, jb, wv, wi)) { wv = db; wi = jb; }
            if (better(dc, jc, wv, wi)) { wv = dc; wi = jc; }
            g_argmin[m] = wi;
            g_dist[m] = wv;
        }
    }
}

// ============================================================================
// Kernel 5: smem-transposed gather — coalesced codebook reads AND output writes.
// ============================================================================
__global__ void __launch_bounds__(256)
gather_kernel(const float* __restrict__ w, float* __restrict__ out) {
    __shared__ float sm[DIM][33];
    __shared__ int js[32];
    const int t = threadIdx.x;
    const int m0 = blockIdx.x * 32;            // grid 2048
    if (t < 32) js[t] = g_argmin[m0 + t];
    __syncthreads();

    #pragma unroll
    for (int p4 = 0; p4 < 32; p4 += 4) {
        float v0 = w[(size_t)js[p4 + 0] * DIM + t];
        float v1 = w[(size_t)js[p4 + 1] * DIM + t];
        float v2 = w[(size_t)js[p4 + 2] * DIM + t];
        float v3 = w[(size_t)js[p4 + 3] * DIM + t];
        sm[t][p4 + 0] = v0;
        sm[t][p4 + 1] = v1;
        sm[t][p4 + 2] = v2;
        sm[t][p4 + 3] = v3;
    }
    __syncthreads();

    const int b = m0 >> 12, hw0 = m0 & (HW - 1);
    float* op = out + (size_t)b * (DIM * HW) + hw0;
    const int lane = t & 31, wrp = t >> 5;
    #pragma unroll
    for (int i = 0; i < 32; ++i) {
        int c = wrp * 32 + i;
        op[(size_t)c * HW + lane] = sm[c][lane];
    }
}

// ============================================================================
// Kernel 6/7: loss = 0.25 * sum_m(dist[m] + xnorm[m]) / TOTAL_ELEMS
// ============================================================================
__global__ void __launch_bounds__(256)
losspart_kernel() {
    __shared__ float red[256];
    const int t = threadIdx.x;
    const int gt = blockIdx.x * 256 + t;     // 16384 threads
    float s = 0.f;
    #pragma unroll
    for (int r = 0; r < 4; ++r) {
        int m = gt + r * 16384;
        float xn = g_dist[m];
        #pragma unroll
        for (int by = 0; by < 8; ++by) xn += g_xnp[by][m];
        s += xn;
    }
    red[t] = s;
    __syncthreads();
    #pragma unroll
    for (int o = 128; o > 0; o >>= 1) {
        if (t < o) red[t] += red[t + o];
        __syncthreads();
    }
    if (t == 0) g_part[blockIdx.x] = red[0];
}

__global__ void __launch_bounds__(64)
finalize_kernel(float* __restrict__ out, int loss_idx) {
    __shared__ float red[64];
    const int t = threadIdx.x;
    red[t] = g_part[t];
    __syncthreads();
    #pragma unroll
    for (int o = 32; o > 0; o >>= 1) {
        if (t < o) red[t] += red[t + o];
        __syncthreads();
    }
    if (t == 0)
        out[loss_idx] = 0.25f * red[0] / (float)TOTAL_ELEMS;
}

// ============================================================================
extern "C" void kernel_launch(void* const* d_in, const int* in_sizes, int n_in,
                              void* d_out, int out_size) {
    const float* x = (const float*)d_in[0];   // [16,256,64,64]
    const float* w = (const float*)d_in[1];   // [2048,256]
    float* out = (float*)d_out;

    cudaFuncSetAttribute(mma_argmin_kernel,
                         cudaFuncAttributeMaxDynamicSharedMemorySize, SM_TOT);

    wprep_kernel<<<NCODE * 32 / 256, 256>>>(w);
    xsplit_kernel<<<dim3(HW / 32, DIM / 32, 16), 256>>>(x);
    mma_argmin_kernel<<<(NVEC / MT) * NSPLIT, NTHR, SM_TOT>>>();
    merge_kernel<<<NVEC / 256, 256>>>();
    rescue_kernel<<<96, 256>>>(x, w);
    gather_kernel<<<NVEC / 32, 256>>>(w, out);
    losspart_kernel<<<64, 256>>>();
    finalize_kernel<<<1, 64>>>(out, out_size - 1);
}